// round 15
// baseline (speedup 1.0000x reference)
#include <cuda_runtime.h>
#include <math.h>

#define NFEAT 8192
#define DIM   768
#define BQ    4096
#define PPK   2048
#define NCLS  256
#define KNN   20
#define TAUF  0.07f

// Scratch (allocation-free rule: device globals)
__device__ float g_fn[NFEAT * DIM];
__device__ float g_hn[BQ * DIM];
__device__ float g_pn[PPK * DIM];
__device__ float g_sim[(size_t)NFEAT * NFEAT];
__device__ float g_logits[(size_t)BQ * PPK];
__device__ float g_dens[NFEAT];
__device__ int   g_knn[NFEAT * KNN];

// ---------------------------------------------------------------------------
// Row L2 normalization == XLA:CPU (aarch64/NEON, LLVM VF=4 IC=2) lowering:
//   8 accumulator chains: chain[c] over x[8i + c], i = 0..95 ascending,
//     UNFUSED:  s = add.rn(s, mul.rn(v, v));
//   IC combine (lanewise):    c_l = add.rn(p0_l, p1_l)   (p1 = chains 4..7)
//   horizontal faddp tree:    s = add.rn(add.rn(c0,c1), add.rn(c2,c3))
//   norm = sqrt.rn(s); out = div.rn(x, norm).
// One warp per row (lanes 0..7 run the chains from a shared copy);
// 8 rows per 256-thread block.
// ---------------------------------------------------------------------------
__global__ void __launch_bounds__(256)
normalize_rows(const float* __restrict__ in, float* __restrict__ out) {
    int gwarp = (blockIdx.x * blockDim.x + threadIdx.x) >> 5;   // row
    int lane  = threadIdx.x & 31;
    int w     = threadIdx.x >> 5;

    __shared__ float sbuf[8][DIM];     // 24 KB
    __shared__ float snrm[8];

    const float* x = in + (size_t)gwarp * DIM;
#pragma unroll
    for (int i = 0; i < DIM / 32; i++)
        sbuf[w][i * 32 + lane] = x[i * 32 + lane];
    __syncwarp();

    // lanes 0..7: unfused chain over x[8i + lane], i ascending
    float ch = 0.0f;
    if (lane < 8) {
#pragma unroll 8
        for (int i = 0; i < DIM / 8; i++) {
            float v = sbuf[w][i * 8 + lane];
            ch = __fadd_rn(ch, __fmul_rn(v, v));
        }
    }
    __syncwarp();

    // lane 0: IC combine + faddp horizontal tree
    float c4 = __shfl_sync(0xffffffffu, ch, (lane & 3) + 4);   // chain[l+4]
    float cl = __fadd_rn(ch, c4);                               // lanes 0..3 hold c_l
    float c0 = __shfl_sync(0xffffffffu, cl, 0);
    float c1 = __shfl_sync(0xffffffffu, cl, 1);
    float c2 = __shfl_sync(0xffffffffu, cl, 2);
    float c3 = __shfl_sync(0xffffffffu, cl, 3);
    if (lane == 0) {
        float s = __fadd_rn(__fadd_rn(c0, c1), __fadd_rn(c2, c3));
        snrm[w] = sqrtf(s);                  // IEEE sqrt.rn
    }
    __syncwarp();
    float nrm = snrm[w];

    float* o = out + (size_t)gwarp * DIM;
#pragma unroll
    for (int i = 0; i < DIM / 32; i++) {
        float v = sbuf[w][i * 32 + lane];
        o[i * 32 + lane] = __fdiv_rn(v, nrm);   // IEEE division per element
    }
}

// ---------------------------------------------------------------------------
// fp32 NT GEMM: C[M][N] = A[M][K] * B[N][K]^T, each output element a single
// sequential fmaf chain over k ascending (bitwise == Eigen gebp single
// k-panel on Grace / cuBLAS SIMT sgemm).
// DIVTAU: epilogue x -> div.rn(x, 0.07f).
// 128x128 tile, BK=16, 256 threads, 8x8 micro. SYM: mirror write.
// ---------------------------------------------------------------------------
template <bool SYM, bool DIVTAU>
__global__ void __launch_bounds__(256)
gemm_nt(const float* __restrict__ A, const float* __restrict__ B,
        float* __restrict__ C, int M, int N, int K) {
    constexpr int BM = 128, BN = 128, BK = 16, TM = 8, TN = 8;
    int bx = blockIdx.x, by = blockIdx.y;
    if (SYM && bx > by) return;

    __shared__ float As[BK][BM];
    __shared__ float Bs[BK][BN];

    int tid  = threadIdx.x;
    int tcol = tid & 15;
    int trow = tid >> 4;

    const float* Ab = A + (size_t)by * BM * K;
    const float* Bb = B + (size_t)bx * BN * K;

    float acc[TM][TN];
#pragma unroll
    for (int m = 0; m < TM; m++)
#pragma unroll
        for (int n = 0; n < TN; n++) acc[m][n] = 0.0f;

    for (int kt = 0; kt < K; kt += BK) {
#pragma unroll
        for (int i = 0; i < 2; i++) {
            int f   = tid + i * 256;
            int row = f >> 2;
            int kq  = (f & 3) << 2;
            float4 va = *(const float4*)(Ab + (size_t)row * K + kt + kq);
            As[kq + 0][row] = va.x; As[kq + 1][row] = va.y;
            As[kq + 2][row] = va.z; As[kq + 3][row] = va.w;
            float4 vb = *(const float4*)(Bb + (size_t)row * K + kt + kq);
            Bs[kq + 0][row] = vb.x; Bs[kq + 1][row] = vb.y;
            Bs[kq + 2][row] = vb.z; Bs[kq + 3][row] = vb.w;
        }
        __syncthreads();
#pragma unroll
        for (int kk = 0; kk < BK; kk++) {
            float a[TM], b[TN];
            *(float4*)&a[0] = *(const float4*)&As[kk][trow * TM];
            *(float4*)&a[4] = *(const float4*)&As[kk][trow * TM + 4];
            *(float4*)&b[0] = *(const float4*)&Bs[kk][tcol * TN];
            *(float4*)&b[4] = *(const float4*)&Bs[kk][tcol * TN + 4];
#pragma unroll
            for (int m = 0; m < TM; m++)
#pragma unroll
                for (int n = 0; n < TN; n++)
                    acc[m][n] = fmaf(a[m], b[n], acc[m][n]);
        }
        __syncthreads();
    }

#pragma unroll
    for (int m = 0; m < TM; m++)
#pragma unroll
        for (int n = 0; n < TN; n++)
            if (DIVTAU) acc[m][n] = __fdiv_rn(acc[m][n], TAUF);

    size_t c0 = (size_t)(by * BM + trow * TM) * N + bx * BN + tcol * TN;
#pragma unroll
    for (int m = 0; m < TM; m++) {
        float4 v0, v1;
        v0.x = acc[m][0]; v0.y = acc[m][1]; v0.z = acc[m][2]; v0.w = acc[m][3];
        v1.x = acc[m][4]; v1.y = acc[m][5]; v1.z = acc[m][6]; v1.w = acc[m][7];
        *(float4*)(C + c0 + (size_t)m * N)     = v0;
        *(float4*)(C + c0 + (size_t)m * N + 4) = v1;
    }
    if (SYM && bx != by) {
        size_t t0 = (size_t)(bx * BN + tcol * TN) * N + by * BM + trow * TM;
#pragma unroll
        for (int n = 0; n < TN; n++) {
            float4 u0, u1;
            u0.x = acc[0][n]; u0.y = acc[1][n]; u0.z = acc[2][n]; u0.w = acc[3][n];
            u1.x = acc[4][n]; u1.y = acc[5][n]; u1.z = acc[6][n]; u1.w = acc[7][n];
            *(float4*)(C + t0 + (size_t)n * N)     = u0;
            *(float4*)(C + t0 + (size_t)n * N + 4) = u1;
        }
    }
}

// ---------------------------------------------------------------------------
// Top-(K+1) per row of g_sim via 21 sequential argmax extractions over a
// shared-memory copy of the row (ties -> lower index, matching
// jax.lax.top_k). Rank 0 (self) dropped.
// density = (sequential fp32 sum of ranks 1..20) / 20.0f (IEEE div).
// ---------------------------------------------------------------------------
__global__ void __launch_bounds__(256)
topk_kernel(float* __restrict__ out_dens, float* __restrict__ out_knnf) {
    int row = blockIdx.x;
    __shared__ float sv[NFEAT];                 // 32 KB
    __shared__ unsigned long long wmax[8];
    __shared__ float svals[KNN + 1];

    const float4* src = (const float4*)(g_sim + (size_t)row * NFEAT);
    float4* dst = (float4*)sv;
    for (int i = threadIdx.x; i < NFEAT / 4; i += 256) dst[i] = src[i];
    __syncthreads();

    for (int r = 0; r < KNN + 1; r++) {
        unsigned long long best = 0ull;
        for (int j = threadIdx.x; j < NFEAT; j += 256) {
            float v = sv[j];
            unsigned u = __float_as_uint(v);
            u = (u & 0x80000000u) ? ~u : (u | 0x80000000u);
            unsigned long long key =
                ((unsigned long long)u << 32) | (unsigned)(NFEAT - 1 - j);
            if (key > best) best = key;
        }
#pragma unroll
        for (int o = 16; o; o >>= 1) {
            unsigned long long other = __shfl_xor_sync(0xffffffffu, best, o);
            if (other > best) best = other;
        }
        if ((threadIdx.x & 31) == 0) wmax[threadIdx.x >> 5] = best;
        __syncthreads();
        if (threadIdx.x == 0) {
            unsigned long long b = wmax[0];
#pragma unroll
            for (int w = 1; w < 8; w++)
                if (wmax[w] > b) b = wmax[w];
            int idx = NFEAT - 1 - (int)(unsigned)(b & 0xffffffffu);
            unsigned enc = (unsigned)(b >> 32);
            unsigned uo = (enc & 0x80000000u) ? (enc ^ 0x80000000u) : ~enc;
            svals[r] = __uint_as_float(uo);
            sv[idx] = -INFINITY;
            if (r >= 1) {
                g_knn[row * KNN + (r - 1)]    = idx;
                out_knnf[row * KNN + (r - 1)] = (float)idx;
            }
        }
        __syncthreads();
    }
    if (threadIdx.x == 0) {
        float s = 0.0f;
        for (int r = 1; r <= KNN; r++) s = __fadd_rn(s, svals[r]);
        float d = __fdiv_rn(s, 20.0f);
        g_dens[row]   = d;
        out_dens[row] = d;
    }
}

// ---------------------------------------------------------------------------
// peak_mask[i] = all_j ( dens[i] > dens[knn[i][j]] )
// ---------------------------------------------------------------------------
__global__ void peak_kernel(float* __restrict__ out_mask) {
    int i = blockIdx.x * blockDim.x + threadIdx.x;
    if (i >= NFEAT) return;
    float di = g_dens[i];
    bool all = true;
#pragma unroll
    for (int j = 0; j < KNN; j++)
        all = all && (di > g_dens[g_knn[i * KNN + j]]);
    out_mask[i] = all ? 1.0f : 0.0f;
}

// ---------------------------------------------------------------------------
// Per-row softmax over 2048 logits + scatter into 256 class bins by label.
// ---------------------------------------------------------------------------
__global__ void __launch_bounds__(256)
softmax_agg(const int* __restrict__ labels, float* __restrict__ out_preds) {
    int b = blockIdx.x, t = threadIdx.x;
    __shared__ float sl[PPK];
    __shared__ int   slab[PPK];
    __shared__ float acc[NCLS];
    __shared__ float red[8];

    for (int i = t; i < PPK; i += 256) {
        sl[i]   = g_logits[(size_t)b * PPK + i];
        slab[i] = labels[i];
    }
    if (t < NCLS) acc[t] = 0.0f;
    __syncthreads();

    float m = -INFINITY;
    for (int i = t; i < PPK; i += 256) m = fmaxf(m, sl[i]);
#pragma unroll
    for (int o = 16; o; o >>= 1) m = fmaxf(m, __shfl_xor_sync(0xffffffffu, m, o));
    if ((t & 31) == 0) red[t >> 5] = m;
    __syncthreads();
    float M = red[0];
#pragma unroll
    for (int w = 1; w < 8; w++) M = fmaxf(M, red[w]);

    float s = 0.0f;
    for (int i = t; i < PPK; i += 256) {
        float e = expf(sl[i] - M);
        s += e;
        atomicAdd(&acc[slab[i]], e);
    }
#pragma unroll
    for (int o = 16; o; o >>= 1) s += __shfl_xor_sync(0xffffffffu, s, o);
    __syncthreads();
    if ((t & 31) == 0) red[t >> 5] = s;
    __syncthreads();
    float S = red[0] + red[1] + red[2] + red[3] + red[4] + red[5] + red[6] + red[7];

    float invS = 1.0f / S;
    if (t < NCLS) out_preds[(size_t)b * NCLS + t] = acc[t] * invS;
}

// ---------------------------------------------------------------------------
extern "C" void kernel_launch(void* const* d_in, const int* in_sizes, int n_in,
                              void* d_out, int out_size) {
    const float* features = nullptr;
    const float* h_i      = nullptr;
    const float* peakf    = nullptr;
    const int*   labels   = nullptr;
    for (int i = 0; i < n_in; i++) {
        long sz = in_sizes[i];
        if      (sz == (long)NFEAT * DIM) features = (const float*)d_in[i];
        else if (sz == (long)BQ * DIM)    h_i      = (const float*)d_in[i];
        else if (sz == (long)PPK * DIM)   peakf    = (const float*)d_in[i];
        else if (sz == (long)PPK)         labels   = (const int*)d_in[i];
    }

    float *fn, *hn, *pn, *sim, *logits;
    cudaGetSymbolAddress((void**)&fn,     g_fn);
    cudaGetSymbolAddress((void**)&hn,     g_hn);
    cudaGetSymbolAddress((void**)&pn,     g_pn);
    cudaGetSymbolAddress((void**)&sim,    g_sim);
    cudaGetSymbolAddress((void**)&logits, g_logits);

    float* out       = (float*)d_out;
    float* out_preds = out;                                  // 4096*256
    float* out_dens  = out_preds + (size_t)BQ * NCLS;        // 8192
    float* out_knn   = out_dens + NFEAT;                     // 8192*20
    float* out_mask  = out_knn + (size_t)NFEAT * KNN;        // 8192

    normalize_rows<<<NFEAT / 8, 256>>>(features, fn);
    normalize_rows<<<BQ / 8,    256>>>(h_i,      hn);
    normalize_rows<<<PPK / 8,   256>>>(peakf,    pn);

    gemm_nt<true,  false><<<dim3(NFEAT / 128, NFEAT / 128), 256>>>(fn, fn, sim,
                                                                   NFEAT, NFEAT, DIM);
    gemm_nt<false, true ><<<dim3(PPK / 128, BQ / 128), 256>>>(hn, pn, logits,
                                                              BQ, PPK, DIM);

    topk_kernel<<<NFEAT, 256>>>(out_dens, out_knn);
    peak_kernel<<<(NFEAT + 255) / 256, 256>>>(out_mask);
    softmax_agg<<<BQ, 256>>>(labels, out_preds);
}

// round 16
// speedup vs baseline: 1.0852x; 1.0852x over previous
#include <cuda_runtime.h>
#include <math.h>

#define NFEAT 8192
#define DIM   768
#define BQ    4096
#define PPK   2048
#define NCLS  256
#define KNN   20
#define TAUF  0.07f

// Scratch (allocation-free rule: device globals)
__device__ float g_fn[NFEAT * DIM];
__device__ float g_hn[BQ * DIM];
__device__ float g_pn[PPK * DIM];
__device__ float g_sim[(size_t)NFEAT * NFEAT];
__device__ float g_logits[(size_t)BQ * PPK];
__device__ float g_dens[NFEAT];
__device__ int   g_knn[NFEAT * KNN];

// ---------------------------------------------------------------------------
// Row L2 normalization == XLA:CPU (aarch64/NEON, LLVM VF=4 IC=2) lowering.
// DO NOT TOUCH: this dataflow is bitwise-matched to the reference (R15 pass).
//   8 accumulator chains: chain[c] over x[8i + c], i ascending, UNFUSED;
//   IC combine c_l = p0_l + p1_l; faddp tree (c0+c1)+(c2+c3);
//   norm = sqrt.rn; out = div.rn(x, norm).
// ---------------------------------------------------------------------------
__global__ void __launch_bounds__(256)
normalize_rows(const float* __restrict__ in, float* __restrict__ out) {
    int gwarp = (blockIdx.x * blockDim.x + threadIdx.x) >> 5;   // row
    int lane  = threadIdx.x & 31;
    int w     = threadIdx.x >> 5;

    __shared__ float sbuf[8][DIM];     // 24 KB
    __shared__ float snrm[8];

    const float* x = in + (size_t)gwarp * DIM;
#pragma unroll
    for (int i = 0; i < DIM / 32; i++)
        sbuf[w][i * 32 + lane] = x[i * 32 + lane];
    __syncwarp();

    float ch = 0.0f;
    if (lane < 8) {
#pragma unroll 8
        for (int i = 0; i < DIM / 8; i++) {
            float v = sbuf[w][i * 8 + lane];
            ch = __fadd_rn(ch, __fmul_rn(v, v));
        }
    }
    __syncwarp();

    float c4 = __shfl_sync(0xffffffffu, ch, (lane & 3) + 4);
    float cl = __fadd_rn(ch, c4);
    float c0 = __shfl_sync(0xffffffffu, cl, 0);
    float c1 = __shfl_sync(0xffffffffu, cl, 1);
    float c2 = __shfl_sync(0xffffffffu, cl, 2);
    float c3 = __shfl_sync(0xffffffffu, cl, 3);
    if (lane == 0) {
        float s = __fadd_rn(__fadd_rn(c0, c1), __fadd_rn(c2, c3));
        snrm[w] = sqrtf(s);
    }
    __syncwarp();
    float nrm = snrm[w];

    float* o = out + (size_t)gwarp * DIM;
#pragma unroll
    for (int i = 0; i < DIM / 32; i++) {
        float v = sbuf[w][i * 32 + lane];
        o[i * 32 + lane] = __fdiv_rn(v, nrm);
    }
}

// ---------------------------------------------------------------------------
// fp32 NT GEMM: C[M][N] = A[M][K] * B[N][K]^T, each output element a single
// sequential fmaf chain over k ascending (bitwise identical to R15's GEMM —
// only the thread->output mapping changed).
// Conflict-free fragment loads: each thread owns 4+4 split spans
// (rows trow*4 & 64+trow*4, cols tcol*4 & 64+tcol*4), so LDS.128 phases
// read contiguous 16B chunks (B) / broadcast (A). Smem rows padded to 132
// floats to reduce staging-store conflicts.
// DIVTAU: epilogue x -> div.rn(x, 0.07f). SYM: mirror write.
// ---------------------------------------------------------------------------
template <bool SYM, bool DIVTAU>
__global__ void __launch_bounds__(256)
gemm_nt(const float* __restrict__ A, const float* __restrict__ B,
        float* __restrict__ C, int M, int N, int K) {
    constexpr int BM = 128, BN = 128, BK = 16, TM = 8, TN = 8, S = 132;
    int bx = blockIdx.x, by = blockIdx.y;
    if (SYM && bx > by) return;

    __shared__ float As[BK][S];
    __shared__ float Bs[BK][S];

    int tid  = threadIdx.x;
    int tcol = tid & 15;
    int trow = tid >> 4;

    const float* Ab = A + (size_t)by * BM * K;
    const float* Bb = B + (size_t)bx * BN * K;

    float acc[TM][TN];
#pragma unroll
    for (int m = 0; m < TM; m++)
#pragma unroll
        for (int n = 0; n < TN; n++) acc[m][n] = 0.0f;

    for (int kt = 0; kt < K; kt += BK) {
#pragma unroll
        for (int i = 0; i < 2; i++) {
            int f   = tid + i * 256;
            int row = f >> 2;
            int kq  = (f & 3) << 2;
            float4 va = *(const float4*)(Ab + (size_t)row * K + kt + kq);
            As[kq + 0][row] = va.x; As[kq + 1][row] = va.y;
            As[kq + 2][row] = va.z; As[kq + 3][row] = va.w;
            float4 vb = *(const float4*)(Bb + (size_t)row * K + kt + kq);
            Bs[kq + 0][row] = vb.x; Bs[kq + 1][row] = vb.y;
            Bs[kq + 2][row] = vb.z; Bs[kq + 3][row] = vb.w;
        }
        __syncthreads();
#pragma unroll
        for (int kk = 0; kk < BK; kk++) {
            float a[TM], b[TN];
            *(float4*)&a[0] = *(const float4*)&As[kk][trow * 4];
            *(float4*)&a[4] = *(const float4*)&As[kk][64 + trow * 4];
            *(float4*)&b[0] = *(const float4*)&Bs[kk][tcol * 4];
            *(float4*)&b[4] = *(const float4*)&Bs[kk][64 + tcol * 4];
#pragma unroll
            for (int m = 0; m < TM; m++)
#pragma unroll
                for (int n = 0; n < TN; n++)
                    acc[m][n] = fmaf(a[m], b[n], acc[m][n]);
        }
        __syncthreads();
    }

#pragma unroll
    for (int m = 0; m < TM; m++)
#pragma unroll
        for (int n = 0; n < TN; n++)
            if (DIVTAU) acc[m][n] = __fdiv_rn(acc[m][n], TAUF);

    // Normal write: rows {trow*4+m | m<4} ∪ {64+trow*4+m-4}, cols split 4+4
#pragma unroll
    for (int m = 0; m < TM; m++) {
        int mr = (m < 4) ? (trow * 4 + m) : (64 + trow * 4 + (m - 4));
        size_t base = (size_t)(by * BM + mr) * N + bx * BN;
        float4 v0, v1;
        v0.x = acc[m][0]; v0.y = acc[m][1]; v0.z = acc[m][2]; v0.w = acc[m][3];
        v1.x = acc[m][4]; v1.y = acc[m][5]; v1.z = acc[m][6]; v1.w = acc[m][7];
        *(float4*)(C + base + tcol * 4)      = v0;
        *(float4*)(C + base + 64 + tcol * 4) = v1;
    }
    // Mirror write for symmetric case
    if (SYM && bx != by) {
#pragma unroll
        for (int n = 0; n < TN; n++) {
            int nc = (n < 4) ? (tcol * 4 + n) : (64 + tcol * 4 + (n - 4));
            size_t base = (size_t)(bx * BN + nc) * N + by * BM;
            float4 u0, u1;
            u0.x = acc[0][n]; u0.y = acc[1][n]; u0.z = acc[2][n]; u0.w = acc[3][n];
            u1.x = acc[4][n]; u1.y = acc[5][n]; u1.z = acc[6][n]; u1.w = acc[7][n];
            *(float4*)(C + base + trow * 4)      = u0;
            *(float4*)(C + base + 64 + trow * 4) = u1;
        }
    }
}

// ---------------------------------------------------------------------------
// Top-(K+1) per row of g_sim via 21 sequential argmax extractions over a
// shared-memory copy of the row (ties -> lower index). Unchanged from R15.
// ---------------------------------------------------------------------------
__global__ void __launch_bounds__(256)
topk_kernel(float* __restrict__ out_dens, float* __restrict__ out_knnf) {
    int row = blockIdx.x;
    __shared__ float sv[NFEAT];                 // 32 KB
    __shared__ unsigned long long wmax[8];
    __shared__ float svals[KNN + 1];

    const float4* src = (const float4*)(g_sim + (size_t)row * NFEAT);
    float4* dst = (float4*)sv;
    for (int i = threadIdx.x; i < NFEAT / 4; i += 256) dst[i] = src[i];
    __syncthreads();

    for (int r = 0; r < KNN + 1; r++) {
        unsigned long long best = 0ull;
        for (int j = threadIdx.x; j < NFEAT; j += 256) {
            float v = sv[j];
            unsigned u = __float_as_uint(v);
            u = (u & 0x80000000u) ? ~u : (u | 0x80000000u);
            unsigned long long key =
                ((unsigned long long)u << 32) | (unsigned)(NFEAT - 1 - j);
            if (key > best) best = key;
        }
#pragma unroll
        for (int o = 16; o; o >>= 1) {
            unsigned long long other = __shfl_xor_sync(0xffffffffu, best, o);
            if (other > best) best = other;
        }
        if ((threadIdx.x & 31) == 0) wmax[threadIdx.x >> 5] = best;
        __syncthreads();
        if (threadIdx.x == 0) {
            unsigned long long b = wmax[0];
#pragma unroll
            for (int w = 1; w < 8; w++)
                if (wmax[w] > b) b = wmax[w];
            int idx = NFEAT - 1 - (int)(unsigned)(b & 0xffffffffu);
            unsigned enc = (unsigned)(b >> 32);
            unsigned uo = (enc & 0x80000000u) ? (enc ^ 0x80000000u) : ~enc;
            svals[r] = __uint_as_float(uo);
            sv[idx] = -INFINITY;
            if (r >= 1) {
                g_knn[row * KNN + (r - 1)]    = idx;
                out_knnf[row * KNN + (r - 1)] = (float)idx;
            }
        }
        __syncthreads();
    }
    if (threadIdx.x == 0) {
        float s = 0.0f;
        for (int r = 1; r <= KNN; r++) s = __fadd_rn(s, svals[r]);
        float d = __fdiv_rn(s, 20.0f);
        g_dens[row]   = d;
        out_dens[row] = d;
    }
}

// ---------------------------------------------------------------------------
// peak_mask[i] = all_j ( dens[i] > dens[knn[i][j]] )
// ---------------------------------------------------------------------------
__global__ void peak_kernel(float* __restrict__ out_mask) {
    int i = blockIdx.x * blockDim.x + threadIdx.x;
    if (i >= NFEAT) return;
    float di = g_dens[i];
    bool all = true;
#pragma unroll
    for (int j = 0; j < KNN; j++)
        all = all && (di > g_dens[g_knn[i * KNN + j]]);
    out_mask[i] = all ? 1.0f : 0.0f;
}

// ---------------------------------------------------------------------------
// Per-row softmax over 2048 logits + scatter into 256 class bins by label.
// ---------------------------------------------------------------------------
__global__ void __launch_bounds__(256)
softmax_agg(const int* __restrict__ labels, float* __restrict__ out_preds) {
    int b = blockIdx.x, t = threadIdx.x;
    __shared__ float sl[PPK];
    __shared__ int   slab[PPK];
    __shared__ float acc[NCLS];
    __shared__ float red[8];

    for (int i = t; i < PPK; i += 256) {
        sl[i]   = g_logits[(size_t)b * PPK + i];
        slab[i] = labels[i];
    }
    if (t < NCLS) acc[t] = 0.0f;
    __syncthreads();

    float m = -INFINITY;
    for (int i = t; i < PPK; i += 256) m = fmaxf(m, sl[i]);
#pragma unroll
    for (int o = 16; o; o >>= 1) m = fmaxf(m, __shfl_xor_sync(0xffffffffu, m, o));
    if ((t & 31) == 0) red[t >> 5] = m;
    __syncthreads();
    float M = red[0];
#pragma unroll
    for (int w = 1; w < 8; w++) M = fmaxf(M, red[w]);

    float s = 0.0f;
    for (int i = t; i < PPK; i += 256) {
        float e = expf(sl[i] - M);
        s += e;
        atomicAdd(&acc[slab[i]], e);
    }
#pragma unroll
    for (int o = 16; o; o >>= 1) s += __shfl_xor_sync(0xffffffffu, s, o);
    __syncthreads();
    if ((t & 31) == 0) red[t >> 5] = s;
    __syncthreads();
    float S = red[0] + red[1] + red[2] + red[3] + red[4] + red[5] + red[6] + red[7];

    float invS = 1.0f / S;
    if (t < NCLS) out_preds[(size_t)b * NCLS + t] = acc[t] * invS;
}

// ---------------------------------------------------------------------------
extern "C" void kernel_launch(void* const* d_in, const int* in_sizes, int n_in,
                              void* d_out, int out_size) {
    const float* features = nullptr;
    const float* h_i      = nullptr;
    const float* peakf    = nullptr;
    const int*   labels   = nullptr;
    for (int i = 0; i < n_in; i++) {
        long sz = in_sizes[i];
        if      (sz == (long)NFEAT * DIM) features = (const float*)d_in[i];
        else if (sz == (long)BQ * DIM)    h_i      = (const float*)d_in[i];
        else if (sz == (long)PPK * DIM)   peakf    = (const float*)d_in[i];
        else if (sz == (long)PPK)         labels   = (const int*)d_in[i];
    }

    float *fn, *hn, *pn, *sim, *logits;
    cudaGetSymbolAddress((void**)&fn,     g_fn);
    cudaGetSymbolAddress((void**)&hn,     g_hn);
    cudaGetSymbolAddress((void**)&pn,     g_pn);
    cudaGetSymbolAddress((void**)&sim,    g_sim);
    cudaGetSymbolAddress((void**)&logits, g_logits);

    float* out       = (float*)d_out;
    float* out_preds = out;                                  // 4096*256
    float* out_dens  = out_preds + (size_t)BQ * NCLS;        // 8192
    float* out_knn   = out_dens + NFEAT;                     // 8192*20
    float* out_mask  = out_knn + (size_t)NFEAT * KNN;        // 8192

    normalize_rows<<<NFEAT / 8, 256>>>(features, fn);
    normalize_rows<<<BQ / 8,    256>>>(h_i,      hn);
    normalize_rows<<<PPK / 8,   256>>>(peakf,    pn);

    gemm_nt<true,  false><<<dim3(NFEAT / 128, NFEAT / 128), 256>>>(fn, fn, sim,
                                                                   NFEAT, NFEAT, DIM);
    gemm_nt<false, true ><<<dim3(PPK / 128, BQ / 128), 256>>>(hn, pn, logits,
                                                              BQ, PPK, DIM);

    topk_kernel<<<NFEAT, 256>>>(out_dens, out_knn);
    peak_kernel<<<(NFEAT + 255) / 256, 256>>>(out_mask);
    softmax_agg<<<BQ, 256>>>(labels, out_preds);
}

// round 17
// speedup vs baseline: 1.2544x; 1.1560x over previous
#include <cuda_runtime.h>
#include <math.h>

#define NFEAT 8192
#define DIM   768
#define BQ    4096
#define PPK   2048
#define NCLS  256
#define KNN   20
#define TAUF  0.07f

// Scratch (allocation-free rule: device globals)
__device__ float g_fn[NFEAT * DIM];
__device__ float g_hn[BQ * DIM];
__device__ float g_pn[PPK * DIM];
__device__ float g_sim[(size_t)NFEAT * NFEAT];
__device__ float g_logits[(size_t)BQ * PPK];
__device__ float g_dens[NFEAT];
__device__ int   g_knn[NFEAT * KNN];

// ---------------------------------------------------------------------------
// Row L2 normalization == XLA:CPU (aarch64/NEON, LLVM VF=4 IC=2) lowering.
// DO NOT TOUCH: bitwise-matched to the reference (R15 pass).
// ---------------------------------------------------------------------------
__global__ void __launch_bounds__(256)
normalize_rows(const float* __restrict__ in, float* __restrict__ out) {
    int gwarp = (blockIdx.x * blockDim.x + threadIdx.x) >> 5;   // row
    int lane  = threadIdx.x & 31;
    int w     = threadIdx.x >> 5;

    __shared__ float sbuf[8][DIM];     // 24 KB
    __shared__ float snrm[8];

    const float* x = in + (size_t)gwarp * DIM;
#pragma unroll
    for (int i = 0; i < DIM / 32; i++)
        sbuf[w][i * 32 + lane] = x[i * 32 + lane];
    __syncwarp();

    float ch = 0.0f;
    if (lane < 8) {
#pragma unroll 8
        for (int i = 0; i < DIM / 8; i++) {
            float v = sbuf[w][i * 8 + lane];
            ch = __fadd_rn(ch, __fmul_rn(v, v));
        }
    }
    __syncwarp();

    float c4 = __shfl_sync(0xffffffffu, ch, (lane & 3) + 4);
    float cl = __fadd_rn(ch, c4);
    float c0 = __shfl_sync(0xffffffffu, cl, 0);
    float c1 = __shfl_sync(0xffffffffu, cl, 1);
    float c2 = __shfl_sync(0xffffffffu, cl, 2);
    float c3 = __shfl_sync(0xffffffffu, cl, 3);
    if (lane == 0) {
        float s = __fadd_rn(__fadd_rn(c0, c1), __fadd_rn(c2, c3));
        snrm[w] = sqrtf(s);
    }
    __syncwarp();
    float nrm = snrm[w];

    float* o = out + (size_t)gwarp * DIM;
#pragma unroll
    for (int i = 0; i < DIM / 32; i++) {
        float v = sbuf[w][i * 32 + lane];
        o[i * 32 + lane] = __fdiv_rn(v, nrm);
    }
}

// ---------------------------------------------------------------------------
// fp32 NT GEMM, double-buffered smem. Each output element remains a single
// sequential fmaf chain over k ascending (bitwise identical to R16's GEMM).
// Conflict-free 4+4 split fragment spans; 132-float padded rows.
// DIVTAU: epilogue x -> div.rn(x, 0.07f). SYM: mirror write.
// ---------------------------------------------------------------------------
template <bool SYM, bool DIVTAU>
__global__ void __launch_bounds__(256, 2)
gemm_nt(const float* __restrict__ A, const float* __restrict__ B,
        float* __restrict__ C, int M, int N, int K) {
    constexpr int BM = 128, BN = 128, BK = 16, TM = 8, TN = 8, S = 132;
    int bx = blockIdx.x, by = blockIdx.y;
    if (SYM && bx > by) return;

    __shared__ float As[2][BK][S];
    __shared__ float Bs[2][BK][S];

    int tid  = threadIdx.x;
    int tcol = tid & 15;
    int trow = tid >> 4;

    // staging coords (fixed per thread)
    int f0  = tid;            int row0 = f0 >> 2;  int kq0 = (f0 & 3) << 2;
    int f1  = tid + 256;      int row1 = f1 >> 2;  int kq1 = (f1 & 3) << 2;

    const float* Ab = A + (size_t)by * BM * K;
    const float* Bb = B + (size_t)bx * BN * K;

    float acc[TM][TN];
#pragma unroll
    for (int m = 0; m < TM; m++)
#pragma unroll
        for (int n = 0; n < TN; n++) acc[m][n] = 0.0f;

    float4 pa0, pa1, pb0, pb1;
    // prefetch tile 0
    pa0 = *(const float4*)(Ab + (size_t)row0 * K + kq0);
    pa1 = *(const float4*)(Ab + (size_t)row1 * K + kq1);
    pb0 = *(const float4*)(Bb + (size_t)row0 * K + kq0);
    pb1 = *(const float4*)(Bb + (size_t)row1 * K + kq1);
    As[0][kq0 + 0][row0] = pa0.x; As[0][kq0 + 1][row0] = pa0.y;
    As[0][kq0 + 2][row0] = pa0.z; As[0][kq0 + 3][row0] = pa0.w;
    As[0][kq1 + 0][row1] = pa1.x; As[0][kq1 + 1][row1] = pa1.y;
    As[0][kq1 + 2][row1] = pa1.z; As[0][kq1 + 3][row1] = pa1.w;
    Bs[0][kq0 + 0][row0] = pb0.x; Bs[0][kq0 + 1][row0] = pb0.y;
    Bs[0][kq0 + 2][row0] = pb0.z; Bs[0][kq0 + 3][row0] = pb0.w;
    Bs[0][kq1 + 0][row1] = pb1.x; Bs[0][kq1 + 1][row1] = pb1.y;
    Bs[0][kq1 + 2][row1] = pb1.z; Bs[0][kq1 + 3][row1] = pb1.w;
    __syncthreads();

    int cur = 0;
    for (int kt = 0; kt < K; kt += BK) {
        bool notlast = (kt + BK < K);
        if (notlast) {
            int kn = kt + BK;
            pa0 = *(const float4*)(Ab + (size_t)row0 * K + kn + kq0);
            pa1 = *(const float4*)(Ab + (size_t)row1 * K + kn + kq1);
            pb0 = *(const float4*)(Bb + (size_t)row0 * K + kn + kq0);
            pb1 = *(const float4*)(Bb + (size_t)row1 * K + kn + kq1);
        }
#pragma unroll
        for (int kk = 0; kk < BK; kk++) {
            float a[TM], b[TN];
            *(float4*)&a[0] = *(const float4*)&As[cur][kk][trow * 4];
            *(float4*)&a[4] = *(const float4*)&As[cur][kk][64 + trow * 4];
            *(float4*)&b[0] = *(const float4*)&Bs[cur][kk][tcol * 4];
            *(float4*)&b[4] = *(const float4*)&Bs[cur][kk][64 + tcol * 4];
#pragma unroll
            for (int m = 0; m < TM; m++)
#pragma unroll
                for (int n = 0; n < TN; n++)
                    acc[m][n] = fmaf(a[m], b[n], acc[m][n]);
        }
        if (notlast) {
            int nb = cur ^ 1;
            As[nb][kq0 + 0][row0] = pa0.x; As[nb][kq0 + 1][row0] = pa0.y;
            As[nb][kq0 + 2][row0] = pa0.z; As[nb][kq0 + 3][row0] = pa0.w;
            As[nb][kq1 + 0][row1] = pa1.x; As[nb][kq1 + 1][row1] = pa1.y;
            As[nb][kq1 + 2][row1] = pa1.z; As[nb][kq1 + 3][row1] = pa1.w;
            Bs[nb][kq0 + 0][row0] = pb0.x; Bs[nb][kq0 + 1][row0] = pb0.y;
            Bs[nb][kq0 + 2][row0] = pb0.z; Bs[nb][kq0 + 3][row0] = pb0.w;
            Bs[nb][kq1 + 0][row1] = pb1.x; Bs[nb][kq1 + 1][row1] = pb1.y;
            Bs[nb][kq1 + 2][row1] = pb1.z; Bs[nb][kq1 + 3][row1] = pb1.w;
            __syncthreads();
            cur = nb;
        }
    }

#pragma unroll
    for (int m = 0; m < TM; m++)
#pragma unroll
        for (int n = 0; n < TN; n++)
            if (DIVTAU) acc[m][n] = __fdiv_rn(acc[m][n], TAUF);

#pragma unroll
    for (int m = 0; m < TM; m++) {
        int mr = (m < 4) ? (trow * 4 + m) : (64 + trow * 4 + (m - 4));
        size_t base = (size_t)(by * BM + mr) * N + bx * BN;
        float4 v0, v1;
        v0.x = acc[m][0]; v0.y = acc[m][1]; v0.z = acc[m][2]; v0.w = acc[m][3];
        v1.x = acc[m][4]; v1.y = acc[m][5]; v1.z = acc[m][6]; v1.w = acc[m][7];
        *(float4*)(C + base + tcol * 4)      = v0;
        *(float4*)(C + base + 64 + tcol * 4) = v1;
    }
    if (SYM && bx != by) {
#pragma unroll
        for (int n = 0; n < TN; n++) {
            int nc = (n < 4) ? (tcol * 4 + n) : (64 + tcol * 4 + (n - 4));
            size_t base = (size_t)(bx * BN + nc) * N + by * BM;
            float4 u0, u1;
            u0.x = acc[0][n]; u0.y = acc[1][n]; u0.z = acc[2][n]; u0.w = acc[3][n];
            u1.x = acc[4][n]; u1.y = acc[5][n]; u1.z = acc[6][n]; u1.w = acc[7][n];
            *(float4*)(C + base + trow * 4)      = u0;
            *(float4*)(C + base + 64 + trow * 4) = u1;
        }
    }
}

// ---------------------------------------------------------------------------
// Incremental top-(K+1): each thread holds 32 row-elements in registers with
// a per-thread running max-key. Per round: block-reduce 256 keys; only the
// winner thread removes its element and rescans. Key encoding and extraction
// order identical to R16 (ties -> lower index; density = extraction-ordered
// sequential fp32 sum / 20, IEEE div) -> outputs bitwise unchanged.
// ---------------------------------------------------------------------------
__device__ __forceinline__ unsigned long long topk_key(float val, int j) {
    unsigned u = __float_as_uint(val);
    u = (u & 0x80000000u) ? ~u : (u | 0x80000000u);
    return ((unsigned long long)u << 32) | (unsigned)(NFEAT - 1 - j);
}

__global__ void __launch_bounds__(256)
topk_kernel(float* __restrict__ out_dens, float* __restrict__ out_knnf) {
    int row  = blockIdx.x;
    int t    = threadIdx.x;
    int lane = t & 31;
    int wrp  = t >> 5;

    const float4* src = (const float4*)(g_sim + (size_t)row * NFEAT);
    float v[32];
#pragma unroll
    for (int i = 0; i < 8; i++) {
        float4 q = src[i * 256 + t];
        v[i * 4 + 0] = q.x; v[i * 4 + 1] = q.y;
        v[i * 4 + 2] = q.z; v[i * 4 + 3] = q.w;
    }

    unsigned long long best = 0ull;
#pragma unroll
    for (int e = 0; e < 32; e++) {
        int j = ((e >> 2) * 256 + t) * 4 + (e & 3);
        unsigned long long k = topk_key(v[e], j);
        if (k > best) best = k;
    }

    __shared__ unsigned long long wred[8];
    __shared__ unsigned long long s_win;
    __shared__ float svals[KNN + 1];

    for (int r = 0; r < KNN + 1; r++) {
        unsigned long long b = best;
#pragma unroll
        for (int off = 16; off; off >>= 1) {
            unsigned long long o = __shfl_xor_sync(0xffffffffu, b, off);
            if (o > b) b = o;
        }
        if (lane == 0) wred[wrp] = b;
        __syncthreads();
        if (t == 0) {
            unsigned long long m = wred[0];
#pragma unroll
            for (int w = 1; w < 8; w++)
                if (wred[w] > m) m = wred[w];
            s_win = m;
            int idx = NFEAT - 1 - (int)(unsigned)(m & 0xffffffffu);
            unsigned enc = (unsigned)(m >> 32);
            unsigned uo = (enc & 0x80000000u) ? (enc ^ 0x80000000u) : ~enc;
            svals[r] = __uint_as_float(uo);
            if (r >= 1) {
                g_knn[row * KNN + (r - 1)]    = idx;
                out_knnf[row * KNN + (r - 1)] = (float)idx;
            }
        }
        __syncthreads();
        unsigned long long win = s_win;
        if (best == win) {
            // remove winning element, recompute local best
#pragma unroll
            for (int e = 0; e < 32; e++) {
                int j = ((e >> 2) * 256 + t) * 4 + (e & 3);
                if (topk_key(v[e], j) == win) v[e] = -INFINITY;
            }
            best = 0ull;
#pragma unroll
            for (int e = 0; e < 32; e++) {
                int j = ((e >> 2) * 256 + t) * 4 + (e & 3);
                unsigned long long k = topk_key(v[e], j);
                if (k > best) best = k;
            }
        }
    }
    if (t == 0) {
        float s = 0.0f;
        for (int r = 1; r <= KNN; r++) s = __fadd_rn(s, svals[r]);
        float d = __fdiv_rn(s, 20.0f);
        g_dens[row]   = d;
        out_dens[row] = d;
    }
}

// ---------------------------------------------------------------------------
// peak_mask[i] = all_j ( dens[i] > dens[knn[i][j]] )
// ---------------------------------------------------------------------------
__global__ void peak_kernel(float* __restrict__ out_mask) {
    int i = blockIdx.x * blockDim.x + threadIdx.x;
    if (i >= NFEAT) return;
    float di = g_dens[i];
    bool all = true;
#pragma unroll
    for (int j = 0; j < KNN; j++)
        all = all && (di > g_dens[g_knn[i * KNN + j]]);
    out_mask[i] = all ? 1.0f : 0.0f;
}

// ---------------------------------------------------------------------------
// Per-row softmax over 2048 logits + scatter into 256 class bins by label.
// ---------------------------------------------------------------------------
__global__ void __launch_bounds__(256)
softmax_agg(const int* __restrict__ labels, float* __restrict__ out_preds) {
    int b = blockIdx.x, t = threadIdx.x;
    __shared__ float sl[PPK];
    __shared__ int   slab[PPK];
    __shared__ float acc[NCLS];
    __shared__ float red[8];

    for (int i = t; i < PPK; i += 256) {
        sl[i]   = g_logits[(size_t)b * PPK + i];
        slab[i] = labels[i];
    }
    if (t < NCLS) acc[t] = 0.0f;
    __syncthreads();

    float m = -INFINITY;
    for (int i = t; i < PPK; i += 256) m = fmaxf(m, sl[i]);
#pragma unroll
    for (int o = 16; o; o >>= 1) m = fmaxf(m, __shfl_xor_sync(0xffffffffu, m, o));
    if ((t & 31) == 0) red[t >> 5] = m;
    __syncthreads();
    float M = red[0];
#pragma unroll
    for (int w = 1; w < 8; w++) M = fmaxf(M, red[w]);

    float s = 0.0f;
    for (int i = t; i < PPK; i += 256) {
        float e = expf(sl[i] - M);
        s += e;
        atomicAdd(&acc[slab[i]], e);
    }
#pragma unroll
    for (int o = 16; o; o >>= 1) s += __shfl_xor_sync(0xffffffffu, s, o);
    __syncthreads();
    if ((t & 31) == 0) red[t >> 5] = s;
    __syncthreads();
    float S = red[0] + red[1] + red[2] + red[3] + red[4] + red[5] + red[6] + red[7];

    float invS = 1.0f / S;
    if (t < NCLS) out_preds[(size_t)b * NCLS + t] = acc[t] * invS;
}

// ---------------------------------------------------------------------------
extern "C" void kernel_launch(void* const* d_in, const int* in_sizes, int n_in,
                              void* d_out, int out_size) {
    const float* features = nullptr;
    const float* h_i      = nullptr;
    const float* peakf    = nullptr;
    const int*   labels   = nullptr;
    for (int i = 0; i < n_in; i++) {
        long sz = in_sizes[i];
        if      (sz == (long)NFEAT * DIM) features = (const float*)d_in[i];
        else if (sz == (long)BQ * DIM)    h_i      = (const float*)d_in[i];
        else if (sz == (long)PPK * DIM)   peakf    = (const float*)d_in[i];
        else if (sz == (long)PPK)         labels   = (const int*)d_in[i];
    }

    float *fn, *hn, *pn, *sim, *logits;
    cudaGetSymbolAddress((void**)&fn,     g_fn);
    cudaGetSymbolAddress((void**)&hn,     g_hn);
    cudaGetSymbolAddress((void**)&pn,     g_pn);
    cudaGetSymbolAddress((void**)&sim,    g_sim);
    cudaGetSymbolAddress((void**)&logits, g_logits);

    float* out       = (float*)d_out;
    float* out_preds = out;                                  // 4096*256
    float* out_dens  = out_preds + (size_t)BQ * NCLS;        // 8192
    float* out_knn   = out_dens + NFEAT;                     // 8192*20
    float* out_mask  = out_knn + (size_t)NFEAT * KNN;        // 8192

    normalize_rows<<<NFEAT / 8, 256>>>(features, fn);
    normalize_rows<<<BQ / 8,    256>>>(h_i,      hn);
    normalize_rows<<<PPK / 8,   256>>>(peakf,    pn);

    gemm_nt<true,  false><<<dim3(NFEAT / 128, NFEAT / 128), 256>>>(fn, fn, sim,
                                                                   NFEAT, NFEAT, DIM);
    gemm_nt<false, true ><<<dim3(PPK / 128, BQ / 128), 256>>>(hn, pn, logits,
                                                              BQ, PPK, DIM);

    topk_kernel<<<NFEAT, 256>>>(out_dens, out_knn);
    peak_kernel<<<(NFEAT + 255) / 256, 256>>>(out_mask);
    softmax_agg<<<BQ, 256>>>(labels, out_preds);
}